// round 11
// baseline (speedup 1.0000x reference)
#include <cuda_runtime.h>
#include <math.h>

#define BATCH 16
#define CCH   512
#define NTOK  3136
#define DD    512
#define TDOUT 256
#define MTOT  (BATCH*NTOK)     // 50176
#define NBLK64 (MTOT/64)       // 784
#define L2EPS 1e-12f

// ---------------- scratch (device globals; no runtime allocation) ------------
__device__ float g_QK[(size_t)MTOT * 1024];  // per token: [0:512)=Q, [512:1024)=K (pre-norm then normalized in place)
__device__ float g_Gpart[NBLK64 * 512];      // per-block partial of sum_n qg_n * Q_n
__device__ float g_sspart[NBLK64];           // per-block partial of sum qg^2
__device__ float g_dyn[MTOT];                // gating logits
__device__ float g_w[MTOT];                  // softmax weights
__device__ float g_G[BATCH * DD];            // global query (already scaled by 1/||qg||)

__device__ __forceinline__ float gelu_f(float x) {
    // exact GELU (approximate=False)
    return 0.5f * x * (1.0f + erff(x * 0.70710678118654752440f));
}

// ---------------- kernel 1: [Q|K] = xt @ [wq|wk] + [bq|bk] -------------------
// A is x in [b, c, n] layout -> xt[m=(b,n), c] = x[b*C*N + c*N + n]
// 128x128x8 fp32 tile, 256 threads, 8x8 per thread.
__global__ __launch_bounds__(256) void k_gemm_qk(
    const float* __restrict__ x,
    const float* __restrict__ wq, const float* __restrict__ bq,
    const float* __restrict__ wk, const float* __restrict__ bk)
{
    __shared__ float As[8][128];
    __shared__ float Bs[8][128];
    const int tid = threadIdx.x;
    const int m0 = blockIdx.x * 128;
    const int J0 = blockIdx.y * 128;          // 0..1023

    const float* wmat; const float* bias; int j0;
    if (J0 < 512) { wmat = wq; bias = bq; j0 = J0; }
    else          { wmat = wk; bias = bk; j0 = J0 - 512; }

    // A loads: each thread owns one fixed row of the tile
    const int a_m  = tid & 127;
    const int a_k0 = tid >> 7;                // 0/1, k = a_k0 + 2*i
    const int gm = m0 + a_m;
    const int b_idx = gm / NTOK;
    const int n_idx = gm - b_idx * NTOK;
    const float* xrow = x + (size_t)b_idx * CCH * NTOK + n_idx;

    // B loads: each thread owns one fixed column
    const int bj  = tid & 127;
    const int bk0 = tid >> 7;

    float acc[8][8];
#pragma unroll
    for (int i = 0; i < 8; i++)
#pragma unroll
        for (int j = 0; j < 8; j++) acc[i][j] = 0.f;

    const int rg = (tid >> 4) * 8;
    const int cg = (tid & 15) * 8;

    for (int kt = 0; kt < CCH; kt += 8) {
#pragma unroll
        for (int i = 0; i < 4; i++) {
            int k = a_k0 + 2 * i;
            As[k][a_m] = xrow[(size_t)(kt + k) * NTOK];
        }
#pragma unroll
        for (int i = 0; i < 4; i++) {
            int k = bk0 + 2 * i;
            Bs[k][bj] = wmat[(size_t)(kt + k) * 512 + j0 + bj];
        }
        __syncthreads();
#pragma unroll
        for (int k = 0; k < 8; k++) {
            float a[8], bb[8];
#pragma unroll
            for (int i = 0; i < 8; i++) a[i] = As[k][rg + i];
#pragma unroll
            for (int j = 0; j < 8; j++) bb[j] = Bs[k][cg + j];
#pragma unroll
            for (int i = 0; i < 8; i++)
#pragma unroll
                for (int j = 0; j < 8; j++) acc[i][j] += a[i] * bb[j];
        }
        __syncthreads();
    }
#pragma unroll
    for (int i = 0; i < 8; i++) {
        size_t row = (size_t)(m0 + rg + i) * 1024;
#pragma unroll
        for (int j = 0; j < 8; j++) {
            g_QK[row + J0 + cg + j] = acc[i][j] + bias[j0 + cg + j];
        }
    }
}

// ---------------- kernel 2: l2norm Q,K in place; qg; partial G, partial ||qg||^2
// 64 tokens per block (3136 % 64 == 0, never crosses batch), one warp per token.
__global__ __launch_bounds__(256) void k_normalize(const float* __restrict__ w_g)
{
    __shared__ float s_wg[512];
    __shared__ float sG[8][512];
    __shared__ float sS[8];
    const int tid  = threadIdx.x;
    const int lane = tid & 31;
    const int warp = tid >> 5;
    for (int i = tid; i < 512; i += 256) s_wg[i] = w_g[i];
    __syncthreads();

    const int m0 = blockIdx.x * 64;

    float Gl[16];
#pragma unroll
    for (int u = 0; u < 16; u++) Gl[u] = 0.f;
    float ssl = 0.f;

    for (int t = warp; t < 64; t += 8) {
        size_t base = (size_t)(m0 + t) * 1024;
        // ---- Q ----
        float q[16];
        float ss = 0.f;
#pragma unroll
        for (int u = 0; u < 16; u++) { q[u] = g_QK[base + lane + 32 * u]; ss += q[u] * q[u]; }
#pragma unroll
        for (int o = 16; o > 0; o >>= 1) ss += __shfl_xor_sync(0xffffffff, ss, o);
        float inv = 1.f / fmaxf(sqrtf(ss), L2EPS);
        float qg = 0.f;
#pragma unroll
        for (int u = 0; u < 16; u++) {
            q[u] *= inv;
            g_QK[base + lane + 32 * u] = q[u];
            qg += q[u] * s_wg[lane + 32 * u];
        }
#pragma unroll
        for (int o = 16; o > 0; o >>= 1) qg += __shfl_xor_sync(0xffffffff, qg, o);
#pragma unroll
        for (int u = 0; u < 16; u++) Gl[u] += qg * q[u];
        ssl += qg * qg;
        // ---- K ----
        float kk[16]; float ssk = 0.f;
#pragma unroll
        for (int u = 0; u < 16; u++) { kk[u] = g_QK[base + 512 + lane + 32 * u]; ssk += kk[u] * kk[u]; }
#pragma unroll
        for (int o = 16; o > 0; o >>= 1) ssk += __shfl_xor_sync(0xffffffff, ssk, o);
        float invk = 1.f / fmaxf(sqrtf(ssk), L2EPS);
#pragma unroll
        for (int u = 0; u < 16; u++) g_QK[base + 512 + lane + 32 * u] = kk[u] * invk;
    }
#pragma unroll
    for (int u = 0; u < 16; u++) sG[warp][lane + 32 * u] = Gl[u];
    if (lane == 0) sS[warp] = ssl;
    __syncthreads();
    for (int j = tid; j < 512; j += 256) {
        float s = 0.f;
#pragma unroll
        for (int w2 = 0; w2 < 8; w2++) s += sG[w2][j];
        g_Gpart[blockIdx.x * 512 + j] = s;
    }
    if (tid == 0) {
        float s = 0.f;
        for (int w2 = 0; w2 < 8; w2++) s += sS[w2];
        g_sspart[blockIdx.x] = s;
    }
}

// ---------------- kernel 3: dyn = gelu(Q@wd1 + bd1) @ wd2 + bd2 --------------
// Fused: 32 token rows x full 512 cols per block, never materializes the
// [M,512] activation. TK=8.
__global__ __launch_bounds__(256) void k_dyn(
    const float* __restrict__ wd1, const float* __restrict__ bd1,
    const float* __restrict__ wd2, const float* __restrict__ bd2)
{
    __shared__ float As[8][32];
    __shared__ float Bs[8][512];
    __shared__ float s_b1[512];
    __shared__ float s_w2[512];
    const int tid = threadIdx.x;
    const int m0  = blockIdx.x * 32;
    for (int i = tid; i < 512; i += 256) { s_b1[i] = bd1[i]; s_w2[i] = wd2[i]; }

    const int lane = tid & 31;
    const int rg   = tid >> 5;        // 0..7 -> rows rg*4..rg*4+3
    float acc[4][16];
#pragma unroll
    for (int r = 0; r < 4; r++)
#pragma unroll
        for (int u = 0; u < 16; u++) acc[r][u] = 0.f;

    const int a_k = tid & 7;
    const int a_r = tid >> 3;         // 0..31
    __syncthreads();

    for (int kt = 0; kt < 512; kt += 8) {
        As[a_k][a_r] = g_QK[(size_t)(m0 + a_r) * 1024 + kt + a_k];
#pragma unroll
        for (int i = 0; i < 16; i++) {
            int e = tid + 256 * i;
            int j = e & 511;
            int k = e >> 9;
            Bs[k][j] = wd1[(size_t)(kt + k) * 512 + j];
        }
        __syncthreads();
#pragma unroll
        for (int k = 0; k < 8; k++) {
            float a0 = As[k][rg * 4 + 0], a1 = As[k][rg * 4 + 1];
            float a2 = As[k][rg * 4 + 2], a3 = As[k][rg * 4 + 3];
#pragma unroll
            for (int u = 0; u < 16; u++) {
                float b = Bs[k][lane + 32 * u];
                acc[0][u] += a0 * b; acc[1][u] += a1 * b;
                acc[2][u] += a2 * b; acc[3][u] += a3 * b;
            }
        }
        __syncthreads();
    }
#pragma unroll
    for (int r = 0; r < 4; r++) {
        float s = 0.f;
#pragma unroll
        for (int u = 0; u < 16; u++) {
            float z = acc[r][u] + s_b1[lane + 32 * u];
            s += gelu_f(z) * s_w2[lane + 32 * u];
        }
#pragma unroll
        for (int o = 16; o > 0; o >>= 1) s += __shfl_xor_sync(0xffffffff, s, o);
        if (lane == 0) g_dyn[m0 + rg * 4 + r] = s + bd2[0];
    }
}

// ---------------- kernel 4: per-batch finalize: G, softmax weights -----------
__global__ __launch_bounds__(256) void k_finalize()
{
    __shared__ float red[256];
    const int b   = blockIdx.x;
    const int tid = threadIdx.x;

    if (tid == 0) {
        float s = 0.f;
        for (int i = 0; i < 49; i++) s += g_sspart[b * 49 + i];
        red[0] = s;
    }
    __syncthreads();
    const float SCALE = 0.0625f;      // 256^-0.5
    float denom = fmaxf(SCALE * sqrtf(red[0]), L2EPS);
    float f = SCALE / denom;
    __syncthreads();

    for (int j = tid; j < 512; j += 256) {
        float s = 0.f;
        for (int i = 0; i < 49; i++) s += g_Gpart[(size_t)(b * 49 + i) * 512 + j];
        g_G[b * 512 + j] = f * s;
    }

    // softmax over tokens (deterministic fixed-order partials + tree)
    float mx = -1e30f;
    for (int n = tid; n < NTOK; n += 256) mx = fmaxf(mx, g_dyn[b * NTOK + n]);
    red[tid] = mx; __syncthreads();
    for (int o = 128; o > 0; o >>= 1) { if (tid < o) red[tid] = fmaxf(red[tid], red[tid + o]); __syncthreads(); }
    mx = red[0]; __syncthreads();

    float se = 0.f;
    for (int n = tid; n < NTOK; n += 256) se += expf(g_dyn[b * NTOK + n] - mx);
    red[tid] = se; __syncthreads();
    for (int o = 128; o > 0; o >>= 1) { if (tid < o) red[tid] += red[tid + o]; __syncthreads(); }
    float inv = 1.f / red[0];
    for (int n = tid; n < NTOK; n += 256)
        g_w[b * NTOK + n] = expf(g_dyn[b * NTOK + n] - mx) * inv;
}

// ---------------- kernel 5: out = gelu(w*G*K + Q) @ wf + bf ------------------
// Transposed tile: 256 output channels (rows) x 64 tokens (cols) so stores into
// [B, 256, H, W] hit 32B-contiguous token runs. 64-token tiles never cross batch.
__global__ __launch_bounds__(256) void k_out(
    const float* __restrict__ wf, const float* __restrict__ bf,
    float* __restrict__ out)
{
    __shared__ float At[8][256];     // wf^T tile: At[k][t]
    __shared__ float Ns[8][64];      // A'^T tile: Ns[k][n] = gelu(w*G*K + Q)
    __shared__ float Gs[512];
    __shared__ float s_bf[256];
    const int tid = threadIdx.x;
    const int m0  = blockIdx.x * 64;
    const int b   = m0 / NTOK;
    const int n0  = m0 - b * NTOK;

    for (int i = tid; i < 512; i += 256) Gs[i] = g_G[b * 512 + i];
    s_bf[tid] = bf[tid];

    const int rg = tid >> 3;          // 0..31 -> t rows rg*8..+7
    const int cg = tid & 7;           // token cols cg + 8*uu

    // A' build coords: k = tid&7, token rows tid>>3 and +32
    const int l_k = tid & 7;
    const int l_n = tid >> 3;
    const size_t row0 = (size_t)(m0 + l_n) * 1024;
    const size_t row1 = (size_t)(m0 + l_n + 32) * 1024;
    const float wn0 = g_w[m0 + l_n];
    const float wn1 = g_w[m0 + l_n + 32];

    float acc[8][8];
#pragma unroll
    for (int i = 0; i < 8; i++)
#pragma unroll
        for (int j = 0; j < 8; j++) acc[i][j] = 0.f;

    __syncthreads();

    for (int kt = 0; kt < 512; kt += 8) {
#pragma unroll
        for (int i = 0; i < 8; i++)
            At[i][tid] = wf[(size_t)(kt + i) * 256 + tid];
        {
            int c = kt + l_k;
            float g = Gs[c];
            float q0 = g_QK[row0 + c], kv0 = g_QK[row0 + 512 + c];
            float q1 = g_QK[row1 + c], kv1 = g_QK[row1 + 512 + c];
            Ns[l_k][l_n]      = gelu_f(wn0 * g * kv0 + q0);
            Ns[l_k][l_n + 32] = gelu_f(wn1 * g * kv1 + q1);
        }
        __syncthreads();
#pragma unroll
        for (int k = 0; k < 8; k++) {
            float a[8], bb[8];
#pragma unroll
            for (int i = 0; i < 8; i++) a[i] = At[k][rg * 8 + i];
#pragma unroll
            for (int j = 0; j < 8; j++) bb[j] = Ns[k][cg + 8 * j];
#pragma unroll
            for (int i = 0; i < 8; i++)
#pragma unroll
                for (int j = 0; j < 8; j++) acc[i][j] += a[i] * bb[j];
        }
        __syncthreads();
    }

#pragma unroll
    for (int i = 0; i < 8; i++) {
        int t = rg * 8 + i;
        float bias = s_bf[t];
        size_t base = ((size_t)b * 256 + t) * NTOK + n0;
#pragma unroll
        for (int j = 0; j < 8; j++) {
            out[base + cg + 8 * j] = acc[i][j] + bias;
        }
    }
}

// -----------------------------------------------------------------------------
extern "C" void kernel_launch(void* const* d_in, const int* in_sizes, int n_in,
                              void* d_out, int out_size)
{
    const float* x   = (const float*)d_in[0];
    const float* wq  = (const float*)d_in[1];
    const float* bq  = (const float*)d_in[2];
    const float* wk  = (const float*)d_in[3];
    const float* bk  = (const float*)d_in[4];
    const float* w_g = (const float*)d_in[5];
    const float* wd1 = (const float*)d_in[6];
    const float* bd1 = (const float*)d_in[7];
    const float* wd2 = (const float*)d_in[8];
    const float* bd2 = (const float*)d_in[9];
    const float* wf  = (const float*)d_in[10];
    const float* bf  = (const float*)d_in[11];
    float* out = (float*)d_out;

    k_gemm_qk<<<dim3(MTOT / 128, 8), 256>>>(x, wq, bq, wk, bk);
    k_normalize<<<NBLK64, 256>>>(w_g);
    k_dyn<<<MTOT / 32, 256>>>(wd1, bd1, wd2, bd2);
    k_finalize<<<BATCH, 256>>>();
    k_out<<<NBLK64, 256>>>(wf, bf, out);
}

// round 14
// speedup vs baseline: 2.3964x; 2.3964x over previous
#include <cuda_runtime.h>
#include <cuda_bf16.h>
#include <math.h>
#include <stdint.h>

#define BATCH 16
#define CCH   512
#define NTOK  3136
#define MTOT  (BATCH*NTOK)     // 50176
#define NBLK64 (MTOT/64)       // 784
#define L2EPS 1e-12f

// ---------------- scratch (device globals; no runtime allocation) ------------
__device__ float g_QK[(size_t)MTOT * 1024];          // GEMM1 out [tok][0:512)=Q, [512:1024)=K (pre-norm)
__device__ __nv_bfloat16 gx_hi[(size_t)MTOT * 512];  // xt split; later reused for gelu-act
__device__ __nv_bfloat16 gx_lo[(size_t)MTOT * 512];
__device__ __nv_bfloat16 gq_hi[(size_t)MTOT * 512];  // normalized Q split
__device__ __nv_bfloat16 gq_lo[(size_t)MTOT * 512];
__device__ __nv_bfloat16 gk_hi[(size_t)MTOT * 512];  // normalized K split
__device__ __nv_bfloat16 gk_lo[(size_t)MTOT * 512];
__device__ __nv_bfloat16 gw_hi[1792 * 512];          // W^T rows: wq 0..511, wk 512..1023, wd1 1024..1535, wf 1536..1791
__device__ __nv_bfloat16 gw_lo[1792 * 512];
__device__ float g_Gpart[NBLK64 * 512];
__device__ float g_sspart[NBLK64];
__device__ float g_dynpart[4 * (size_t)MTOT];
__device__ float g_dyn[MTOT];
__device__ float g_w[MTOT];
__device__ float g_G[BATCH * 512];

__device__ __forceinline__ float gelu_f(float x) {
    return 0.5f * x * (1.0f + erff(x * 0.70710678118654752440f));
}

// ---------------- PTX helpers (baseline PTX only — no arch-specific ops) -----
__device__ __forceinline__ uint32_t smem_u32(const void* p) {
    uint32_t a;
    asm("{ .reg .u64 t; cvta.to.shared.u64 t, %1; cvt.u32.u64 %0, t; }" : "=r"(a) : "l"(p));
    return a;
}
__device__ __forceinline__ void cpa16(uint32_t s, const void* g) {
    asm volatile("cp.async.cg.shared.global [%0], [%1], 16;" :: "r"(s), "l"(g));
}
__device__ __forceinline__ void ldsm4(uint32_t* r, uint32_t addr) {
    asm volatile("ldmatrix.sync.aligned.m8n8.x4.shared.b16 {%0,%1,%2,%3}, [%4];"
                 : "=r"(r[0]), "=r"(r[1]), "=r"(r[2]), "=r"(r[3]) : "r"(addr));
}
__device__ __forceinline__ void mma16816(float* d, const uint32_t* a, const uint32_t* b) {
    asm volatile(
        "mma.sync.aligned.m16n8k16.row.col.f32.bf16.bf16.f32 "
        "{%0,%1,%2,%3}, {%4,%5,%6,%7}, {%8,%9}, {%0,%1,%2,%3};"
        : "+f"(d[0]), "+f"(d[1]), "+f"(d[2]), "+f"(d[3])
        : "r"(a[0]), "r"(a[1]), "r"(a[2]), "r"(a[3]), "r"(b[0]), "r"(b[1]));
}
__device__ __forceinline__ void split_bf16(float x, __nv_bfloat16& h, __nv_bfloat16& l) {
    h = __float2bfloat16(x);
    l = __float2bfloat16(x - __bfloat162float(h));
}

// ---------------- weights: transpose to [N][K] rows + split ------------------
__global__ __launch_bounds__(256) void k_prep_w(
    const float* __restrict__ wq, const float* __restrict__ wk,
    const float* __restrict__ wd1, const float* __restrict__ wf)
{
    __shared__ float sm[32][33];
    const int tx = threadIdx.x, ty = threadIdx.y;
    const float* W; int N, r0;
    switch (blockIdx.z) {
        case 0: W = wq;  N = 512; r0 = 0;    break;
        case 1: W = wk;  N = 512; r0 = 512;  break;
        case 2: W = wd1; N = 512; r0 = 1024; break;
        default: W = wf; N = 256; r0 = 1536; break;
    }
    const int k0 = blockIdx.x * 32, n0 = blockIdx.y * 32;
    if (n0 >= N) return;
#pragma unroll
    for (int i = 0; i < 4; i++)
        sm[ty + 8 * i][tx] = W[(size_t)(k0 + ty + 8 * i) * N + n0 + tx];
    __syncthreads();
#pragma unroll
    for (int i = 0; i < 4; i++) {
        int n = n0 + ty + 8 * i;
        float v = sm[tx][ty + 8 * i];
        size_t o = (size_t)(r0 + n) * 512 + k0 + tx;
        __nv_bfloat16 h, l; split_bf16(v, h, l);
        gw_hi[o] = h; gw_lo[o] = l;
    }
}

// ---------------- transpose + split x -> xt hi/lo [M,512] --------------------
__global__ __launch_bounds__(256) void k_prep_x(const float* __restrict__ x)
{
    __shared__ float sm[32][33];
    const int tx = threadIdx.x, ty = threadIdx.y;
    const int b = blockIdx.z, c0 = blockIdx.y * 32, n0 = blockIdx.x * 32;
    const float* xb = x + ((size_t)b * CCH + c0) * NTOK + n0;
#pragma unroll
    for (int i = 0; i < 4; i++)
        sm[ty + 8 * i][tx] = xb[(size_t)(ty + 8 * i) * NTOK + tx];
    __syncthreads();
#pragma unroll
    for (int i = 0; i < 4; i++) {
        int r = ty + 8 * i;
        float v = sm[tx][r];
        size_t o = (size_t)(b * NTOK + n0 + r) * 512 + c0 + tx;
        __nv_bfloat16 h, l; split_bf16(v, h, l);
        gx_hi[o] = h; gx_lo[o] = l;
    }
}

// ---------------- mma.sync split-bf16 GEMM (CTA tile 128x128, K=512) ---------
// MODE 0: QK  (A=gx,  B rows bx*128 in 0..1023,   epi: +bias -> g_QK)
// MODE 1: DYN (A=gq,  B rows 1024 + bx*128,        epi: gelu(+bd1)*wd2 row-sum -> g_dynpart)
// MODE 2: OUT (A=gx(=act), B rows 1536 + bx*128,   epi: +bf -> transposed out)
#define APITCH 80            // bytes per smem row (32 bf16 data + 16B pad): ldmatrix conflict-free
#define STG_BYTES 40960      // 4 matrices * 128 rows * 80B
#define SMEM_SZ (2 * STG_BYTES)

template <int MODE>
__global__ __launch_bounds__(256, 1) void k_gemm_mma(
    const float* __restrict__ p0, const float* __restrict__ p1,
    float* __restrict__ outp)
{
    extern __shared__ char smem[];
    const uint32_t sb = smem_u32(smem);
    const int tid  = threadIdx.x;
    const int lane = tid & 31;
    const int wid  = tid >> 5;
    const int wm   = wid >> 2;   // 0..1 -> 64 rows each
    const int wn   = wid & 3;    // 0..3 -> 32 cols each
    const int m0   = blockIdx.y * 128;
    const int bx   = blockIdx.x;
    const int brow = (MODE == 0 ? 0 : (MODE == 1 ? 1024 : 1536)) + bx * 128;

    const __nv_bfloat16* a_hi = (MODE == 1) ? gq_hi : gx_hi;
    const __nv_bfloat16* a_lo = (MODE == 1) ? gq_lo : gx_lo;

    // ldmatrix per-lane base offsets (A row-major m16k16; B [n][k] "col" operand)
    const uint32_t aOff = (uint32_t)((wm * 64 + (lane & 15)) * APITCH + (lane >> 4) * 16);
    const uint32_t bOff = (uint32_t)((wn * 32 + (lane & 7) + ((lane >> 4) << 3)) * APITCH
                                     + ((lane >> 3) & 1) * 16);

    float acc[4][4][4];
#pragma unroll
    for (int mt = 0; mt < 4; mt++)
#pragma unroll
        for (int nt = 0; nt < 4; nt++)
#pragma unroll
            for (int k = 0; k < 4; k++) acc[mt][nt][k] = 0.f;

    auto loadChunk = [&](int c, int s) {
        const int kt = c * 32;
        const uint32_t base = sb + s * STG_BYTES;
#pragma unroll
        for (int i = 0; i < 2; i++) {
            int e = tid + 256 * i;
            int row = e >> 2, seg = e & 3;
            uint32_t d = base + (uint32_t)(row * APITCH + seg * 16);
            size_t ga = (size_t)(m0 + row) * 512 + kt + seg * 8;
            cpa16(d,         a_hi + ga);
            cpa16(d + 10240, a_lo + ga);
            size_t gb = (size_t)(brow + row) * 512 + kt + seg * 8;
            cpa16(d + 20480, gw_hi + gb);
            cpa16(d + 30720, gw_lo + gb);
        }
        asm volatile("cp.async.commit_group;" ::: "memory");
    };

    loadChunk(0, 0);
    for (int c = 0; c < 16; c++) {
        asm volatile("cp.async.wait_group 0;" ::: "memory");
        __syncthreads();
        if (c < 15) loadChunk(c + 1, (c + 1) & 1);
        const uint32_t base = sb + (c & 1) * STG_BYTES;
#pragma unroll
        for (int ks = 0; ks < 2; ks++) {
            uint32_t ah[4][4], al[4][4], bh[8], bl[8];
            const uint32_t aB = base + aOff + ks * 32;
#pragma unroll
            for (int mt = 0; mt < 4; mt++) {
                ldsm4(ah[mt], aB + mt * 16 * APITCH);
                ldsm4(al[mt], aB + 10240 + mt * 16 * APITCH);
            }
            const uint32_t bB = base + 20480 + bOff + ks * 32;
#pragma unroll
            for (int p = 0; p < 2; p++) {
                ldsm4(&bh[4 * p], bB + p * 16 * APITCH);
                ldsm4(&bl[4 * p], bB + 10240 + p * 16 * APITCH);
            }
#pragma unroll
            for (int mt = 0; mt < 4; mt++)
#pragma unroll
                for (int nt = 0; nt < 4; nt++) {
                    mma16816(acc[mt][nt], ah[mt], &bh[2 * nt]);
                    mma16816(acc[mt][nt], ah[mt], &bl[2 * nt]);
                    mma16816(acc[mt][nt], al[mt], &bh[2 * nt]);
                }
        }
        __syncthreads();
    }

    // ---- epilogue ----
    const int r0w = wm * 64 + (lane >> 2);
    const int c0w = wn * 32 + (lane & 3) * 2;

    if (MODE == 0) {
        float* sf = (float*)smem;
#pragma unroll
        for (int mt = 0; mt < 4; mt++)
#pragma unroll
            for (int nt = 0; nt < 4; nt++)
#pragma unroll
                for (int k = 0; k < 4; k++) {
                    int r  = r0w + mt * 16 + ((k >> 1) << 3);
                    int cc = c0w + nt * 8 + (k & 1);
                    sf[r * 132 + cc] = acc[mt][nt][k];
                }
        __syncthreads();
        for (int r = wid; r < 128; r += 8) {
            int c4 = lane * 4;
            float4 v = *(float4*)&sf[r * 132 + c4];
            int jg = bx * 128 + c4;
            if (jg < 512) {
                v.x += __ldg(p0 + jg); v.y += __ldg(p0 + jg + 1);
                v.z += __ldg(p0 + jg + 2); v.w += __ldg(p0 + jg + 3);
            } else {
                int j2 = jg - 512;
                v.x += __ldg(p1 + j2); v.y += __ldg(p1 + j2 + 1);
                v.z += __ldg(p1 + j2 + 2); v.w += __ldg(p1 + j2 + 3);
            }
            *(float4*)&g_QK[(size_t)(m0 + r) * 1024 + jg] = v;
        }
    } else if (MODE == 1) {
        float* sred = (float*)smem;          // [4][128]
        const int cbase = bx * 128 + c0w;
#pragma unroll
        for (int mt = 0; mt < 4; mt++) {
            float sA = 0.f, sB = 0.f;
#pragma unroll
            for (int nt = 0; nt < 4; nt++)
#pragma unroll
                for (int k = 0; k < 4; k++) {
                    int col = cbase + nt * 8 + (k & 1);
                    float z = acc[mt][nt][k] + __ldg(p0 + col);
                    float v = gelu_f(z) * __ldg(p1 + col);
                    if (k < 2) sA += v; else sB += v;
                }
            sA += __shfl_xor_sync(0xffffffff, sA, 1);
            sA += __shfl_xor_sync(0xffffffff, sA, 2);
            sB += __shfl_xor_sync(0xffffffff, sB, 1);
            sB += __shfl_xor_sync(0xffffffff, sB, 2);
            if ((lane & 3) == 0) {
                int r = r0w + mt * 16;
                sred[wn * 128 + r]     = sA;
                sred[wn * 128 + r + 8] = sB;
            }
        }
        __syncthreads();
        if (tid < 128) {
            float s = sred[tid] + sred[128 + tid] + sred[256 + tid] + sred[384 + tid];
            g_dynpart[(size_t)bx * MTOT + m0 + tid] = s;
        }
    } else {
        float* sf = (float*)smem;            // transposed: [ch][tok] pitch 132
#pragma unroll
        for (int mt = 0; mt < 4; mt++)
#pragma unroll
            for (int nt = 0; nt < 4; nt++)
#pragma unroll
                for (int k = 0; k < 4; k++) {
                    int r  = r0w + mt * 16 + ((k >> 1) << 3);
                    int cc = c0w + nt * 8 + (k & 1);
                    sf[cc * 132 + r] = acc[mt][nt][k];
                }
        __syncthreads();
        for (int ch = wid; ch < 128; ch += 8) {
            int t4 = lane * 4;
            float4 v = *(float4*)&sf[ch * 132 + t4];
            int chg = bx * 128 + ch;
            float bias = __ldg(p0 + chg);
            v.x += bias; v.y += bias; v.z += bias; v.w += bias;
            int m = m0 + t4;
            int b = m / NTOK;
            int n = m - b * NTOK;
            *(float4*)&outp[((size_t)b * 256 + chg) * NTOK + n] = v;
        }
    }
}

// ---------------- l2norm Q,K -> bf16 splits; qg partials ---------------------
__global__ __launch_bounds__(256) void k_normalize(const float* __restrict__ w_g)
{
    __shared__ float s_wg[512];
    __shared__ float sG[8][512];
    __shared__ float sS[8];
    const int tid  = threadIdx.x;
    const int lane = tid & 31;
    const int warp = tid >> 5;
    for (int i = tid; i < 512; i += 256) s_wg[i] = w_g[i];
    __syncthreads();

    const int m0 = blockIdx.x * 64;

    float Gl[16];
#pragma unroll
    for (int u = 0; u < 16; u++) Gl[u] = 0.f;
    float ssl = 0.f;

    for (int t = warp; t < 64; t += 8) {
        const int m = m0 + t;
        size_t base  = (size_t)m * 1024;
        size_t sbase = (size_t)m * 512;
        // ---- Q ----
        float q[16];
        float ss = 0.f;
#pragma unroll
        for (int u = 0; u < 16; u++) { q[u] = g_QK[base + lane + 32 * u]; ss += q[u] * q[u]; }
#pragma unroll
        for (int o = 16; o > 0; o >>= 1) ss += __shfl_xor_sync(0xffffffff, ss, o);
        float inv = 1.f / fmaxf(sqrtf(ss), L2EPS);
        float qg = 0.f;
#pragma unroll
        for (int u = 0; u < 16; u++) {
            q[u] *= inv;
            __nv_bfloat16 h, l; split_bf16(q[u], h, l);
            gq_hi[sbase + lane + 32 * u] = h;
            gq_lo[sbase + lane + 32 * u] = l;
            qg += q[u] * s_wg[lane + 32 * u];
        }
#pragma unroll
        for (int o = 16; o > 0; o >>= 1) qg += __shfl_xor_sync(0xffffffff, qg, o);
#pragma unroll
        for (int u = 0; u < 16; u++) Gl[u] += qg * q[u];
        ssl += qg * qg;
        // ---- K ----
        float kk[16]; float ssk = 0.f;
#pragma unroll
        for (int u = 0; u < 16; u++) { kk[u] = g_QK[base + 512 + lane + 32 * u]; ssk += kk[u] * kk[u]; }
#pragma unroll
        for (int o = 16; o > 0; o >>= 1) ssk += __shfl_xor_sync(0xffffffff, ssk, o);
        float invk = 1.f / fmaxf(sqrtf(ssk), L2EPS);
#pragma unroll
        for (int u = 0; u < 16; u++) {
            __nv_bfloat16 h, l; split_bf16(kk[u] * invk, h, l);
            gk_hi[sbase + lane + 32 * u] = h;
            gk_lo[sbase + lane + 32 * u] = l;
        }
    }
#pragma unroll
    for (int u = 0; u < 16; u++) sG[warp][lane + 32 * u] = Gl[u];
    if (lane == 0) sS[warp] = ssl;
    __syncthreads();
    for (int j = tid; j < 512; j += 256) {
        float s = 0.f;
#pragma unroll
        for (int w2 = 0; w2 < 8; w2++) s += sG[w2][j];
        g_Gpart[blockIdx.x * 512 + j] = s;
    }
    if (tid == 0) {
        float s = 0.f;
        for (int w2 = 0; w2 < 8; w2++) s += sS[w2];
        g_sspart[blockIdx.x] = s;
    }
}

// ---------------- per-batch finalize: G, dyn assembly, softmax ---------------
__global__ __launch_bounds__(256) void k_finalize(const float* __restrict__ bd2)
{
    __shared__ float red[256];
    const int b   = blockIdx.x;
    const int tid = threadIdx.x;
    const float bd2v = bd2[0];

    if (tid == 0) {
        float s = 0.f;
        for (int i = 0; i < 49; i++) s += g_sspart[b * 49 + i];
        red[0] = s;
    }
    __syncthreads();
    const float SCALE = 0.0625f;      // 256^-0.5
    float denom = fmaxf(SCALE * sqrtf(red[0]), L2EPS);
    float f = SCALE / denom;
    __syncthreads();

    for (int j = tid; j < 512; j += 256) {
        float s = 0.f;
        for (int i = 0; i < 49; i++) s += g_Gpart[(size_t)(b * 49 + i) * 512 + j];
        g_G[b * 512 + j] = f * s;
    }

    // assemble dyn = sum of 4 N-block partials + bd2, track max
    float mx = -1e30f;
    for (int n = tid; n < NTOK; n += 256) {
        size_t idx = (size_t)b * NTOK + n;
        float v = g_dynpart[idx] + g_dynpart[(size_t)MTOT + idx]
                + g_dynpart[2 * (size_t)MTOT + idx] + g_dynpart[3 * (size_t)MTOT + idx] + bd2v;
        g_dyn[idx] = v;
        mx = fmaxf(mx, v);
    }
    red[tid] = mx; __syncthreads();
    for (int o = 128; o > 0; o >>= 1) { if (tid < o) red[tid] = fmaxf(red[tid], red[tid + o]); __syncthreads(); }
    mx = red[0]; __syncthreads();

    float se = 0.f;
    for (int n = tid; n < NTOK; n += 256) se += expf(g_dyn[b * NTOK + n] - mx);
    red[tid] = se; __syncthreads();
    for (int o = 128; o > 0; o >>= 1) { if (tid < o) red[tid] += red[tid + o]; __syncthreads(); }
    float inv = 1.f / red[0];
    for (int n = tid; n < NTOK; n += 256)
        g_w[b * NTOK + n] = expf(g_dyn[b * NTOK + n] - mx) * inv;
}

// ---------------- act = gelu(w*G*K + Q), split into gx buffers ---------------
__global__ __launch_bounds__(256) void k_prep_act()
{
    __shared__ float Gs[512];
    const int tid  = threadIdx.x;
    const int lane = tid & 31;
    const int warp = tid >> 5;
    const int m0 = blockIdx.x * 64;
    const int b  = m0 / NTOK;
    for (int i = tid; i < 512; i += 256) Gs[i] = g_G[b * 512 + i];
    __syncthreads();

    for (int t = warp; t < 64; t += 8) {
        const int m = m0 + t;
        const float w = g_w[m];
        size_t sbase = (size_t)m * 512;
#pragma unroll
        for (int u = 0; u < 16; u++) {
            int c = lane + 32 * u;
            float q = __bfloat162float(gq_hi[sbase + c]) + __bfloat162float(gq_lo[sbase + c]);
            float k = __bfloat162float(gk_hi[sbase + c]) + __bfloat162float(gk_lo[sbase + c]);
            float a = gelu_f(w * Gs[c] * k + q);
            __nv_bfloat16 h, l; split_bf16(a, h, l);
            gx_hi[sbase + c] = h;
            gx_lo[sbase + c] = l;
        }
    }
}

// -----------------------------------------------------------------------------
extern "C" void kernel_launch(void* const* d_in, const int* in_sizes, int n_in,
                              void* d_out, int out_size)
{
    const float* x   = (const float*)d_in[0];
    const float* wq  = (const float*)d_in[1];
    const float* bq  = (const float*)d_in[2];
    const float* wk  = (const float*)d_in[3];
    const float* bk  = (const float*)d_in[4];
    const float* w_g = (const float*)d_in[5];
    const float* wd1 = (const float*)d_in[6];
    const float* bd1 = (const float*)d_in[7];
    const float* wd2 = (const float*)d_in[8];
    const float* bd2 = (const float*)d_in[9];
    const float* wf  = (const float*)d_in[10];
    const float* bf  = (const float*)d_in[11];
    float* out = (float*)d_out;

    cudaFuncSetAttribute(k_gemm_mma<0>, cudaFuncAttributeMaxDynamicSharedMemorySize, SMEM_SZ);
    cudaFuncSetAttribute(k_gemm_mma<1>, cudaFuncAttributeMaxDynamicSharedMemorySize, SMEM_SZ);
    cudaFuncSetAttribute(k_gemm_mma<2>, cudaFuncAttributeMaxDynamicSharedMemorySize, SMEM_SZ);

    k_prep_w<<<dim3(16, 16, 4), dim3(32, 8)>>>(wq, wk, wd1, wf);
    k_prep_x<<<dim3(98, 16, 16), dim3(32, 8)>>>(x);
    k_gemm_mma<0><<<dim3(8, MTOT / 128), 256, SMEM_SZ>>>(bq, bk, nullptr);
    k_normalize<<<NBLK64, 256>>>(w_g);
    k_gemm_mma<1><<<dim3(4, MTOT / 128), 256, SMEM_SZ>>>(bd1, wd2, nullptr);
    k_finalize<<<BATCH, 256>>>(bd2);
    k_prep_act<<<NBLK64, 256>>>();
    k_gemm_mma<2><<<dim3(2, MTOT / 128), 256, SMEM_SZ>>>(bf, nullptr, out);
}